// round 1
// baseline (speedup 1.0000x reference)
#include <cuda_runtime.h>

#define SEQ   8192
#define DIM   64
#define WIN   64            // half window
#define QPB   128           // queries per block
#define KROWS (QPB + 2*WIN) // 256 key rows staged in smem
#define NTHREADS 128
#define SMEM_BYTES (KROWS * DIM * 4 * 2)   // K + V tiles = 131072 B

typedef unsigned long long ull;

__device__ __forceinline__ ull pk2(float lo, float hi) {
    ull r; asm("mov.b64 %0,{%1,%2};" : "=l"(r) : "f"(lo), "f"(hi)); return r;
}
__device__ __forceinline__ void upk2(ull a, float& lo, float& hi) {
    asm("mov.b64 {%0,%1},%2;" : "=f"(lo), "=f"(hi) : "l"(a));
}
__device__ __forceinline__ ull ffma2(ull a, ull b, ull c) {
    ull d; asm("fma.rn.f32x2 %0,%1,%2,%3;" : "=l"(d) : "l"(a), "l"(b), "l"(c)); return d;
}

__global__ void __launch_bounds__(NTHREADS, 1)
swa_kernel(const float* __restrict__ q, const float* __restrict__ k,
           const float* __restrict__ v, float* __restrict__ out)
{
    extern __shared__ float smem[];
    float* ks = smem;               // [KROWS][DIM]
    float* vs = smem + KROWS * DIM; // [KROWS][DIM]

    const int tilesPerB = SEQ / QPB;
    const int b  = blockIdx.x / tilesPerB;
    const int Q0 = (blockIdx.x % tilesPerB) * QPB;

    const float* qb = q + (size_t)b * SEQ * DIM;
    const float* kb = k + (size_t)b * SEQ * DIM;
    const float* vb = v + (size_t)b * SEQ * DIM;
    float*       ob = out + (size_t)b * SEQ * DIM;

    // ---- stage K/V tile: rows [Q0-64, Q0+191], zero-filled out of range ----
    const int t = threadIdx.x;
    for (int idx = t; idx < KROWS * (DIM / 4); idx += NTHREADS) {
        int r  = idx / (DIM / 4);
        int c4 = idx % (DIM / 4);
        int j  = Q0 - WIN + r;
        float4 kv4 = make_float4(0.f, 0.f, 0.f, 0.f);
        float4 vv4 = make_float4(0.f, 0.f, 0.f, 0.f);
        if (j >= 0 && j < SEQ) {
            kv4 = ((const float4*)(kb + (size_t)j * DIM))[c4];
            vv4 = ((const float4*)(vb + (size_t)j * DIM))[c4];
        }
        ((float4*)(ks + r * DIM))[c4] = kv4;
        ((float4*)(vs + r * DIM))[c4] = vv4;
    }
    __syncthreads();

    const int warpId = t >> 5;
    const int L      = t & 31;
    const int s      = Q0 + warpId * 32 + L;   // this lane's query index

    // ---- q row into packed f32x2 registers ----
    ull q2[32];
    {
        const ulonglong2* qrow = (const ulonglong2*)(qb + (size_t)s * DIM);
        #pragma unroll
        for (int i = 0; i < 16; i++) {
            ulonglong2 qq = qrow[i];
            q2[2*i]   = qq.x;
            q2[2*i+1] = qq.y;
        }
    }

    ull o2[32];
    #pragma unroll
    for (int i = 0; i < 32; i++) o2[i] = 0ull;
    float lsum = 0.f;

    const int   rbase = warpId * 32;          // smem row of warp's first key
    const int   j0    = Q0 - WIN + rbase;     // global key index at w = 0
    const float scale = 0.125f;               // 1/sqrt(64)

    // warp-shared key loop: 160 keys cover all 32 lanes' 129-wide windows
    #pragma unroll 2
    for (int w = 0; w < 2 * WIN + 32; w++) {
        const ulonglong2* krow = (const ulonglong2*)(ks + (size_t)(rbase + w) * DIM);
        ull a0 = 0, a1 = 0, a2 = 0, a3 = 0;
        #pragma unroll
        for (int i = 0; i < 8; i++) {
            ulonglong2 kk0 = krow[2*i];
            ulonglong2 kk1 = krow[2*i + 1];
            a0 = ffma2(q2[4*i+0], kk0.x, a0);
            a1 = ffma2(q2[4*i+1], kk0.y, a1);
            a2 = ffma2(q2[4*i+2], kk1.x, a2);
            a3 = ffma2(q2[4*i+3], kk1.y, a3);
        }
        float s0, s1, s2, s3, s4, s5, s6, s7;
        upk2(a0, s0, s1); upk2(a1, s2, s3);
        upk2(a2, s4, s5); upk2(a3, s6, s7);
        float sc = ((s0 + s1) + (s2 + s3)) + ((s4 + s5) + (s6 + s7));

        int  j  = j0 + w;
        bool ok = (w >= L) && (w <= L + 2 * WIN) && (j >= 0) && (j < SEQ);
        float p = ok ? __expf(sc * scale) : 0.f;
        lsum += p;

        ull p2 = pk2(p, p);
        const ulonglong2* vrow = (const ulonglong2*)(vs + (size_t)(rbase + w) * DIM);
        #pragma unroll
        for (int i = 0; i < 8; i++) {
            ulonglong2 vv0 = vrow[2*i];
            ulonglong2 vv1 = vrow[2*i + 1];
            o2[4*i+0] = ffma2(p2, vv0.x, o2[4*i+0]);
            o2[4*i+1] = ffma2(p2, vv0.y, o2[4*i+1]);
            o2[4*i+2] = ffma2(p2, vv1.x, o2[4*i+2]);
            o2[4*i+3] = ffma2(p2, vv1.y, o2[4*i+3]);
        }
    }

    // ---- normalize and store ----
    float inv = 1.f / lsum;
    #pragma unroll
    for (int i = 0; i < 16; i++) {
        float x, y, z, w2;
        upk2(o2[2*i],   x, y);
        upk2(o2[2*i+1], z, w2);
        float4 o4 = make_float4(x * inv, y * inv, z * inv, w2 * inv);
        ((float4*)(ob + (size_t)s * DIM))[i] = o4;
    }
}

extern "C" void kernel_launch(void* const* d_in, const int* in_sizes, int n_in,
                              void* d_out, int out_size)
{
    const float* q = (const float*)d_in[0];
    const float* k = (const float*)d_in[1];
    const float* v = (const float*)d_in[2];
    float* out = (float*)d_out;

    int B = in_sizes[0] / (SEQ * DIM);

    cudaFuncSetAttribute(swa_kernel,
                         cudaFuncAttributeMaxDynamicSharedMemorySize, SMEM_BYTES);

    dim3 grid(B * (SEQ / QPB));
    swa_kernel<<<grid, NTHREADS, SMEM_BYTES>>>(q, k, v, out);
}

// round 2
// speedup vs baseline: 1.3960x; 1.3960x over previous
#include <cuda_runtime.h>

#define SEQ   8192
#define DIM   64
#define WIN   64                // half window
#define QPB   128               // queries per block
#define KROWS (QPB + 2*WIN)     // 256 key rows staged in smem
#define NTHREADS 256            // 8 warps: 4 query-groups x 2 window-halves
#define HSTEPS 80               // steps per half-window warp (160 total / 2)
#define CB_STRIDE 72            // combine-buffer row stride (floats), 16B-aligned rows
#define KV_BYTES   (KROWS * DIM * 4 * 2)            // 131072
#define SMEM_BYTES (KV_BYTES + QPB * CB_STRIDE * 4) // +36864 = 167936

typedef unsigned long long ull;

__device__ __forceinline__ ull pk2(float lo, float hi) {
    ull r; asm("mov.b64 %0,{%1,%2};" : "=l"(r) : "f"(lo), "f"(hi)); return r;
}
__device__ __forceinline__ void upk2(ull a, float& lo, float& hi) {
    asm("mov.b64 {%0,%1},%2;" : "=f"(lo), "=f"(hi) : "l"(a));
}
__device__ __forceinline__ ull ffma2(ull a, ull b, ull c) {
    ull d; asm("fma.rn.f32x2 %0,%1,%2,%3;" : "=l"(d) : "l"(a), "l"(b), "l"(c)); return d;
}
__device__ __forceinline__ ull fadd2(ull a, ull b) {
    ull d; asm("add.rn.f32x2 %0,%1,%2;" : "=l"(d) : "l"(a), "l"(b)); return d;
}
__device__ __forceinline__ float ex2f(float x) {
    float r; asm("ex2.approx.f32 %0,%1;" : "=f"(r) : "f"(x)); return r;
}

__global__ void __launch_bounds__(NTHREADS, 1)
swa_kernel(const float* __restrict__ q, const float* __restrict__ k,
           const float* __restrict__ v, float* __restrict__ out)
{
    extern __shared__ float smem[];
    float* ks = smem;                 // [KROWS][DIM]
    float* vs = smem + KROWS * DIM;   // [KROWS][DIM]
    float* cb = smem + 2 * KROWS * DIM; // combine buffer [QPB][CB_STRIDE]

    const int tilesPerB = SEQ / QPB;
    const int b  = blockIdx.x / tilesPerB;
    const int Q0 = (blockIdx.x % tilesPerB) * QPB;

    const float* qb = q + (size_t)b * SEQ * DIM;
    const float* kb = k + (size_t)b * SEQ * DIM;
    const float* vb = v + (size_t)b * SEQ * DIM;
    float*       ob = out + (size_t)b * SEQ * DIM;

    // ---- stage K/V tile: rows [Q0-64, Q0+191], zero-filled out of range ----
    const int t = threadIdx.x;
    for (int idx = t; idx < KROWS * (DIM / 4); idx += NTHREADS) {
        int r  = idx / (DIM / 4);
        int c4 = idx % (DIM / 4);
        int j  = Q0 - WIN + r;
        float4 kv4 = make_float4(0.f, 0.f, 0.f, 0.f);
        float4 vv4 = make_float4(0.f, 0.f, 0.f, 0.f);
        if (j >= 0 && j < SEQ) {
            kv4 = ((const float4*)(kb + (size_t)j * DIM))[c4];
            vv4 = ((const float4*)(vb + (size_t)j * DIM))[c4];
        }
        ((float4*)(ks + r * DIM))[c4] = kv4;
        ((float4*)(vs + r * DIM))[c4] = vv4;
    }
    __syncthreads();

    const int wid = t >> 5;
    const int L   = t & 31;
    const int g   = wid & 3;     // query group (4 per block)
    const int h   = wid >> 2;    // window half (0 = low, 1 = high)
    const int qi  = g * 32 + L;  // query index within block
    const int s   = Q0 + qi;     // global query index

    // ---- q row into packed f32x2 regs, prescaled by 1/sqrt(D) * log2(e) ----
    const float PRE = 0.125f * 1.4426950408889634f;
    ull q2[32];
    {
        const float4* qrow = (const float4*)(qb + (size_t)s * DIM);
        #pragma unroll
        for (int i = 0; i < 16; i++) {
            float4 qq = qrow[i];
            q2[2*i]   = pk2(qq.x * PRE, qq.y * PRE);
            q2[2*i+1] = pk2(qq.z * PRE, qq.w * PRE);
        }
    }

    ull o2[32];
    #pragma unroll
    for (int i = 0; i < 32; i++) o2[i] = 0ull;
    float lsum = 0.f;

    const int rbase  = g * 32;           // smem row of this group's first key
    const int j0     = Q0 - WIN + rbase; // global key index at w = 0
    const int wstart = h * HSTEPS;

    // valid w range for this lane within its half-window
    const int wlo = max(wstart, max((int)L, -j0));
    const int whi = min(wstart + HSTEPS - 1, min(L + 2 * WIN, SEQ - 1 - j0));

    #pragma unroll 2
    for (int ww = 0; ww < HSTEPS; ww++) {
        const int w = wstart + ww;
        const ulonglong2* krow = (const ulonglong2*)(ks + (size_t)(rbase + w) * DIM);
        ull a0 = 0, a1 = 0, a2 = 0, a3 = 0;
        #pragma unroll
        for (int i = 0; i < 8; i++) {
            ulonglong2 kk0 = krow[2*i];
            ulonglong2 kk1 = krow[2*i + 1];
            a0 = ffma2(q2[4*i+0], kk0.x, a0);
            a1 = ffma2(q2[4*i+1], kk0.y, a1);
            a2 = ffma2(q2[4*i+2], kk1.x, a2);
            a3 = ffma2(q2[4*i+3], kk1.y, a3);
        }
        a0 = fadd2(a0, a1);
        a2 = fadd2(a2, a3);
        a0 = fadd2(a0, a2);
        float sl, sh;
        upk2(a0, sl, sh);
        float sc = sl + sh;          // score * (1/sqrt(D))*log2(e)

        float e = ex2f(sc);
        float p = (w >= wlo && w <= whi) ? e : 0.f;
        lsum += p;

        ull p2 = pk2(p, p);
        const ulonglong2* vrow = (const ulonglong2*)(vs + (size_t)(rbase + w) * DIM);
        #pragma unroll
        for (int i = 0; i < 8; i++) {
            ulonglong2 vv0 = vrow[2*i];
            ulonglong2 vv1 = vrow[2*i + 1];
            o2[4*i+0] = ffma2(p2, vv0.x, o2[4*i+0]);
            o2[4*i+1] = ffma2(p2, vv0.y, o2[4*i+1]);
            o2[4*i+2] = ffma2(p2, vv1.x, o2[4*i+2]);
            o2[4*i+3] = ffma2(p2, vv1.y, o2[4*i+3]);
        }
    }

    // ---- combine halves: upper writes partial, lower merges + stores ----
    if (h == 1) {
        float* prow = cb + (size_t)qi * CB_STRIDE;
        ulonglong2* p2v = (ulonglong2*)prow;
        #pragma unroll
        for (int i = 0; i < 16; i++) {
            ulonglong2 u; u.x = o2[2*i]; u.y = o2[2*i+1];
            p2v[i] = u;
        }
        prow[64] = lsum;
    }
    __syncthreads();
    if (h == 0) {
        const float* prow = cb + (size_t)qi * CB_STRIDE;
        const ulonglong2* p2v = (const ulonglong2*)prow;
        #pragma unroll
        for (int i = 0; i < 16; i++) {
            ulonglong2 u = p2v[i];
            o2[2*i]   = fadd2(o2[2*i],   u.x);
            o2[2*i+1] = fadd2(o2[2*i+1], u.y);
        }
        lsum += prow[64];

        float inv = 1.f / lsum;
        float4* orow = (float4*)(ob + (size_t)s * DIM);
        #pragma unroll
        for (int i = 0; i < 16; i++) {
            float x, y, z, w2;
            upk2(o2[2*i],   x, y);
            upk2(o2[2*i+1], z, w2);
            orow[i] = make_float4(x * inv, y * inv, z * inv, w2 * inv);
        }
    }
}

extern "C" void kernel_launch(void* const* d_in, const int* in_sizes, int n_in,
                              void* d_out, int out_size)
{
    const float* q = (const float*)d_in[0];
    const float* k = (const float*)d_in[1];
    const float* v = (const float*)d_in[2];
    float* out = (float*)d_out;

    int B = in_sizes[0] / (SEQ * DIM);

    cudaFuncSetAttribute(swa_kernel,
                         cudaFuncAttributeMaxDynamicSharedMemorySize, SMEM_BYTES);

    dim3 grid(B * (SEQ / QPB));
    swa_kernel<<<grid, NTHREADS, SMEM_BYTES>>>(q, k, v, out);
}

// round 4
// speedup vs baseline: 3.0175x; 2.1615x over previous
#include <cuda_runtime.h>
#include <cstdint>

#define SEQ 8192
#define DIM 64
#define WIN 64
#define QPB 128
#define NTHREADS 256
#define ROWB 144            // smem row stride bytes: 64 halfs + 8 pad halfs

#define QH_OFF 0
#define QL_OFF (QH_OFF + 128*ROWB)
#define KH_OFF (QL_OFF + 128*ROWB)
#define KL_OFF (KH_OFF + 256*ROWB)
#define VH_OFF (KL_OFF + 256*ROWB)
#define VL_OFF (VH_OFF + 256*ROWB)
#define SMEM_BYTES (VL_OFF + 256*ROWB)   // 184320

__device__ __forceinline__ uint32_t smem_u32(const void* p) {
    uint32_t a; asm("{ .reg .u64 t; cvta.to.shared.u64 t, %1; cvt.u32.u64 %0, t; }" : "=r"(a) : "l"(p));
    return a;
}
__device__ __forceinline__ float ex2f(float x) { float r; asm("ex2.approx.f32 %0,%1;" : "=f"(r) : "f"(x)); return r; }
__device__ __forceinline__ uint32_t pack_bf16x2(float hi, float lo) {
    uint32_t r; asm("cvt.rn.bf16x2.f32 %0,%1,%2;" : "=r"(r) : "f"(hi), "f"(lo)); return r;
}
// split (a,b) fp32 pair into bf16 hi pair {lo:a,hi:b} (truncation) + bf16 lo (residual) pair
__device__ __forceinline__ void split2(float a, float b, uint32_t& h, uint32_t& l) {
    uint32_t ba = __float_as_uint(a) & 0xFFFF0000u;
    uint32_t bb = __float_as_uint(b) & 0xFFFF0000u;
    h = __byte_perm(ba, bb, 0x7632);
    l = pack_bf16x2(b - __uint_as_float(bb), a - __uint_as_float(ba));
}

__device__ __forceinline__ void ldsm4(uint32_t r[4], uint32_t addr) {
    asm volatile("ldmatrix.sync.aligned.m8n8.x4.shared.b16 {%0,%1,%2,%3}, [%4];"
        : "=r"(r[0]), "=r"(r[1]), "=r"(r[2]), "=r"(r[3]) : "r"(addr));
}
__device__ __forceinline__ void ldsm2(uint32_t& r0, uint32_t& r1, uint32_t addr) {
    asm volatile("ldmatrix.sync.aligned.m8n8.x2.shared.b16 {%0,%1}, [%2];"
        : "=r"(r0), "=r"(r1) : "r"(addr));
}
__device__ __forceinline__ void ldsm2t(uint32_t& r0, uint32_t& r1, uint32_t addr) {
    asm volatile("ldmatrix.sync.aligned.m8n8.x2.trans.shared.b16 {%0,%1}, [%2];"
        : "=r"(r0), "=r"(r1) : "r"(addr));
}
__device__ __forceinline__ void mma_bf16(float c[4], const uint32_t a[4], uint32_t b0, uint32_t b1) {
    asm volatile("mma.sync.aligned.m16n8k16.row.col.f32.bf16.bf16.f32 "
        "{%0,%1,%2,%3}, {%4,%5,%6,%7}, {%8,%9}, {%0,%1,%2,%3};"
        : "+f"(c[0]), "+f"(c[1]), "+f"(c[2]), "+f"(c[3])
        : "r"(a[0]), "r"(a[1]), "r"(a[2]), "r"(a[3]), "r"(b0), "r"(b1));
}

__global__ void __launch_bounds__(NTHREADS, 1)
swa_hmma_kernel(const float* __restrict__ q, const float* __restrict__ k,
                const float* __restrict__ v, float* __restrict__ out)
{
    extern __shared__ char smem[];
    const uint32_t sb = smem_u32(smem);
    const int t = threadIdx.x;

    const int tilesPerB = SEQ / QPB;
    const int b  = blockIdx.x / tilesPerB;
    const int Q0 = (blockIdx.x % tilesPerB) * QPB;

    const float* qb = q + (size_t)b * SEQ * DIM;
    const float* kb = k + (size_t)b * SEQ * DIM;
    const float* vb = v + (size_t)b * SEQ * DIM;
    float*       ob = out + (size_t)b * SEQ * DIM;

    // ---- stage Q (prescaled) as bf16 hi/lo ----
    const float PRE = 0.125f * 1.4426950408889634f;   // 1/sqrt(D) * log2(e)
    for (int idx = t; idx < 128 * 16; idx += NTHREADS) {
        int r = idx >> 4, c4 = idx & 15;
        float4 f = ((const float4*)(qb + (size_t)(Q0 + r) * DIM))[c4];
        f.x *= PRE; f.y *= PRE; f.z *= PRE; f.w *= PRE;
        uint32_t h01, l01, h23, l23;
        split2(f.x, f.y, h01, l01);
        split2(f.z, f.w, h23, l23);
        *(uint2*)(smem + QH_OFF + r * ROWB + c4 * 8) = make_uint2(h01, h23);
        *(uint2*)(smem + QL_OFF + r * ROWB + c4 * 8) = make_uint2(l01, l23);
    }
    // ---- stage K and V rows [Q0-64, Q0+192), zero-filled out of range ----
    for (int idx = t; idx < 256 * 16; idx += NTHREADS) {
        int r = idx >> 4, c4 = idx & 15;
        int j = Q0 - WIN + r;
        float4 kk = make_float4(0.f, 0.f, 0.f, 0.f);
        float4 vv = make_float4(0.f, 0.f, 0.f, 0.f);
        if (j >= 0 && j < SEQ) {
            kk = ((const float4*)(kb + (size_t)j * DIM))[c4];
            vv = ((const float4*)(vb + (size_t)j * DIM))[c4];
        }
        uint32_t h01, l01, h23, l23;
        split2(kk.x, kk.y, h01, l01); split2(kk.z, kk.w, h23, l23);
        *(uint2*)(smem + KH_OFF + r * ROWB + c4 * 8) = make_uint2(h01, h23);
        *(uint2*)(smem + KL_OFF + r * ROWB + c4 * 8) = make_uint2(l01, l23);
        split2(vv.x, vv.y, h01, l01); split2(vv.z, vv.w, h23, l23);
        *(uint2*)(smem + VH_OFF + r * ROWB + c4 * 8) = make_uint2(h01, h23);
        *(uint2*)(smem + VL_OFF + r * ROWB + c4 * 8) = make_uint2(l01, l23);
    }
    __syncthreads();

    const int w = t >> 5;          // warp: owns queries Q0+w*16 .. +15
    const int l = t & 31;

    // ---- load Q A-fragments (4 k-steps, hi+lo) ----
    uint32_t aqh[4][4], aql[4][4];
    {
        uint32_t qaddr = sb + QH_OFF + (uint32_t)(w * 16 + (l & 15)) * ROWB + ((l >> 4) * 16);
        #pragma unroll
        for (int ks = 0; ks < 4; ks++) {
            ldsm4(aqh[ks], qaddr + ks * 32);
            ldsm4(aql[ks], qaddr + (QL_OFF - QH_OFF) + ks * 32);
        }
    }

    // ---- S = Q K^T over 144-key span: 18 n-tiles x 4 k-steps x 3 products ----
    float sacc[18][4];
    #pragma unroll
    for (int nt = 0; nt < 18; nt++)
        #pragma unroll
        for (int i = 0; i < 4; i++) sacc[nt][i] = 0.f;

    {
        uint32_t kaddr = sb + KH_OFF + (uint32_t)(w * 16 + (l & 7)) * ROWB + ((l >> 3) & 1) * 16;
        #pragma unroll
        for (int nt = 0; nt < 18; nt++) {
            #pragma unroll
            for (int ks = 0; ks < 4; ks++) {
                uint32_t a0 = kaddr + (uint32_t)nt * 8 * ROWB + ks * 32;
                uint32_t bh0, bh1, bl0, bl1;
                ldsm2(bh0, bh1, a0);
                ldsm2(bl0, bl1, a0 + (KL_OFF - KH_OFF));
                mma_bf16(sacc[nt], aqh[ks], bh0, bh1);
                mma_bf16(sacc[nt], aqh[ks], bl0, bl1);
                mma_bf16(sacc[nt], aql[ks], bh0, bh1);
            }
        }
    }

    // ---- masked exp + row sums (scores already in log2 domain) ----
    const int jbase = Q0 - WIN + w * 16;
    const int m0 = l >> 2;
    const int cc = (l & 3) * 2;
    float rs0 = 0.f, rs1 = 0.f;
    #pragma unroll
    for (int nt = 0; nt < 18; nt++) {
        int lk = nt * 8 + cc;
        bool ok0a = ((unsigned)(lk     - m0) <= 2u * WIN) && ((unsigned)(jbase + lk)     < SEQ);
        bool ok0b = ((unsigned)(lk + 1 - m0) <= 2u * WIN) && ((unsigned)(jbase + lk + 1) < SEQ);
        bool ok1a = ((unsigned)(lk     - m0 - 8) <= 2u * WIN) && ((unsigned)(jbase + lk)     < SEQ);
        bool ok1b = ((unsigned)(lk + 1 - m0 - 8) <= 2u * WIN) && ((unsigned)(jbase + lk + 1) < SEQ);
        float p0 = ok0a ? ex2f(sacc[nt][0]) : 0.f;
        float p1 = ok0b ? ex2f(sacc[nt][1]) : 0.f;
        float p2 = ok1a ? ex2f(sacc[nt][2]) : 0.f;
        float p3 = ok1b ? ex2f(sacc[nt][3]) : 0.f;
        sacc[nt][0] = p0; sacc[nt][1] = p1; sacc[nt][2] = p2; sacc[nt][3] = p3;
        rs0 += p0 + p1;
        rs1 += p2 + p3;
    }
    rs0 += __shfl_xor_sync(0xFFFFFFFFu, rs0, 1);
    rs0 += __shfl_xor_sync(0xFFFFFFFFu, rs0, 2);
    rs1 += __shfl_xor_sync(0xFFFFFFFFu, rs1, 1);
    rs1 += __shfl_xor_sync(0xFFFFFFFFu, rs1, 2);

    // ---- O = P V : 9 k-steps x 8 n-tiles x 3 products ----
    float oacc[8][4];
    #pragma unroll
    for (int nt = 0; nt < 8; nt++)
        #pragma unroll
        for (int i = 0; i < 4; i++) oacc[nt][i] = 0.f;

    {
        uint32_t vaddr = sb + VH_OFF + (uint32_t)(w * 16 + (l & 7) + ((l >> 3) & 1) * 8) * ROWB;
        #pragma unroll
        for (int ks = 0; ks < 9; ks++) {
            uint32_t ah[4], al[4];
            split2(sacc[2*ks][0],   sacc[2*ks][1],   ah[0], al[0]);
            split2(sacc[2*ks][2],   sacc[2*ks][3],   ah[1], al[1]);
            split2(sacc[2*ks+1][0], sacc[2*ks+1][1], ah[2], al[2]);
            split2(sacc[2*ks+1][2], sacc[2*ks+1][3], ah[3], al[3]);
            #pragma unroll
            for (int nt = 0; nt < 8; nt++) {
                uint32_t a0 = vaddr + (uint32_t)ks * 16 * ROWB + nt * 16;
                uint32_t bh0, bh1, bl0, bl1;
                ldsm2t(bh0, bh1, a0);
                ldsm2t(bl0, bl1, a0 + (VL_OFF - VH_OFF));
                mma_bf16(oacc[nt], ah, bh0, bh1);
                mma_bf16(oacc[nt], ah, bl0, bl1);
                mma_bf16(oacc[nt], al, bh0, bh1);
            }
        }
    }

    // ---- normalize + store ----
    float inv0 = 1.f / rs0;
    float inv1 = 1.f / rs1;
    float* orow0 = ob + (size_t)(Q0 + w * 16 + m0) * DIM;
    float* orow1 = orow0 + 8 * DIM;
    #pragma unroll
    for (int nt = 0; nt < 8; nt++) {
        *(float2*)(orow0 + nt * 8 + cc) = make_float2(oacc[nt][0] * inv0, oacc[nt][1] * inv0);
        *(float2*)(orow1 + nt * 8 + cc) = make_float2(oacc[nt][2] * inv1, oacc[nt][3] * inv1);
    }
}

extern "C" void kernel_launch(void* const* d_in, const int* in_sizes, int n_in,
                              void* d_out, int out_size)
{
    const float* q = (const float*)d_in[0];
    const float* k = (const float*)d_in[1];
    const float* v = (const float*)d_in[2];
    float* out = (float*)d_out;

    int B = in_sizes[0] / (SEQ * DIM);

    cudaFuncSetAttribute(swa_hmma_kernel,
                         cudaFuncAttributeMaxDynamicSharedMemorySize, SMEM_BYTES);

    dim3 grid(B * (SEQ / QPB));
    swa_hmma_kernel<<<grid, NTHREADS, SMEM_BYTES>>>(q, k, v, out);
}

// round 5
// speedup vs baseline: 3.3499x; 1.1102x over previous
#include <cuda_runtime.h>
#include <cstdint>

#define SEQ 8192
#define DIM 64
#define WIN 64
#define QPB 128
#define NTHREADS 512
#define ROWB 144            // smem row stride bytes: 64 halfs + 8 pad halfs

#define QH_OFF 0
#define QL_OFF (QH_OFF + 128*ROWB)
#define KH_OFF (QL_OFF + 128*ROWB)
#define KL_OFF (KH_OFF + 256*ROWB)
#define VH_OFF (KL_OFF + 256*ROWB)
#define VL_OFF (VH_OFF + 256*ROWB)
#define SMEM_BYTES (VL_OFF + 256*ROWB)   // 184320
#define CBS 68              // combine-buffer row stride in floats (272B)

__device__ __forceinline__ uint32_t smem_u32(const void* p) {
    uint32_t a; asm("{ .reg .u64 t; cvta.to.shared.u64 t, %1; cvt.u32.u64 %0, t; }" : "=r"(a) : "l"(p));
    return a;
}
__device__ __forceinline__ float ex2f(float x) { float r; asm("ex2.approx.f32 %0,%1;" : "=f"(r) : "f"(x)); return r; }
__device__ __forceinline__ uint32_t pack_bf16x2(float hi, float lo) {
    uint32_t r; asm("cvt.rn.bf16x2.f32 %0,%1,%2;" : "=r"(r) : "f"(hi), "f"(lo)); return r;
}
// split (a,b) fp32 pair into bf16 hi pair {lo:a,hi:b} (truncation) + bf16 lo (residual) pair
__device__ __forceinline__ void split2(float a, float b, uint32_t& h, uint32_t& l) {
    uint32_t ba = __float_as_uint(a) & 0xFFFF0000u;
    uint32_t bb = __float_as_uint(b) & 0xFFFF0000u;
    h = __byte_perm(ba, bb, 0x7632);
    l = pack_bf16x2(b - __uint_as_float(bb), a - __uint_as_float(ba));
}

__device__ __forceinline__ void ldsm4(uint32_t r[4], uint32_t addr) {
    asm volatile("ldmatrix.sync.aligned.m8n8.x4.shared.b16 {%0,%1,%2,%3}, [%4];"
        : "=r"(r[0]), "=r"(r[1]), "=r"(r[2]), "=r"(r[3]) : "r"(addr));
}
__device__ __forceinline__ void ldsm2(uint32_t& r0, uint32_t& r1, uint32_t addr) {
    asm volatile("ldmatrix.sync.aligned.m8n8.x2.shared.b16 {%0,%1}, [%2];"
        : "=r"(r0), "=r"(r1) : "r"(addr));
}
__device__ __forceinline__ void ldsm2t(uint32_t& r0, uint32_t& r1, uint32_t addr) {
    asm volatile("ldmatrix.sync.aligned.m8n8.x2.trans.shared.b16 {%0,%1}, [%2];"
        : "=r"(r0), "=r"(r1) : "r"(addr));
}
__device__ __forceinline__ void mma_bf16(float c[4], const uint32_t a[4], uint32_t b0, uint32_t b1) {
    asm volatile("mma.sync.aligned.m16n8k16.row.col.f32.bf16.bf16.f32 "
        "{%0,%1,%2,%3}, {%4,%5,%6,%7}, {%8,%9}, {%0,%1,%2,%3};"
        : "+f"(c[0]), "+f"(c[1]), "+f"(c[2]), "+f"(c[3])
        : "r"(a[0]), "r"(a[1]), "r"(a[2]), "r"(a[3]), "r"(b0), "r"(b1));
}

__global__ void __launch_bounds__(NTHREADS, 1)
swa_hmma_kernel(const float* __restrict__ q, const float* __restrict__ k,
                const float* __restrict__ v, float* __restrict__ out)
{
    extern __shared__ char smem[];
    const uint32_t sb = smem_u32(smem);
    const int t = threadIdx.x;

    const int tilesPerB = SEQ / QPB;
    const int b  = blockIdx.x / tilesPerB;
    const int Q0 = (blockIdx.x % tilesPerB) * QPB;

    const float* qb = q + (size_t)b * SEQ * DIM;
    const float* kb = k + (size_t)b * SEQ * DIM;
    const float* vb = v + (size_t)b * SEQ * DIM;
    float*       ob = out + (size_t)b * SEQ * DIM;

    // ---- stage Q (prescaled) as bf16 hi/lo ----
    const float PRE = 0.125f * 1.4426950408889634f;   // 1/sqrt(D) * log2(e)
    for (int idx = t; idx < 128 * 16; idx += NTHREADS) {
        int r = idx >> 4, c4 = idx & 15;
        float4 f = ((const float4*)(qb + (size_t)(Q0 + r) * DIM))[c4];
        f.x *= PRE; f.y *= PRE; f.z *= PRE; f.w *= PRE;
        uint32_t h01, l01, h23, l23;
        split2(f.x, f.y, h01, l01);
        split2(f.z, f.w, h23, l23);
        *(uint2*)(smem + QH_OFF + r * ROWB + c4 * 8) = make_uint2(h01, h23);
        *(uint2*)(smem + QL_OFF + r * ROWB + c4 * 8) = make_uint2(l01, l23);
    }
    // ---- stage K and V rows [Q0-64, Q0+192), zero-filled out of range ----
    for (int idx = t; idx < 256 * 16; idx += NTHREADS) {
        int r = idx >> 4, c4 = idx & 15;
        int j = Q0 - WIN + r;
        float4 kk = make_float4(0.f, 0.f, 0.f, 0.f);
        float4 vv = make_float4(0.f, 0.f, 0.f, 0.f);
        if (j >= 0 && j < SEQ) {
            kk = ((const float4*)(kb + (size_t)j * DIM))[c4];
            vv = ((const float4*)(vb + (size_t)j * DIM))[c4];
        }
        uint32_t h01, l01, h23, l23;
        split2(kk.x, kk.y, h01, l01); split2(kk.z, kk.w, h23, l23);
        *(uint2*)(smem + KH_OFF + r * ROWB + c4 * 8) = make_uint2(h01, h23);
        *(uint2*)(smem + KL_OFF + r * ROWB + c4 * 8) = make_uint2(l01, l23);
        split2(vv.x, vv.y, h01, l01); split2(vv.z, vv.w, h23, l23);
        *(uint2*)(smem + VH_OFF + r * ROWB + c4 * 8) = make_uint2(h01, h23);
        *(uint2*)(smem + VL_OFF + r * ROWB + c4 * 8) = make_uint2(l01, l23);
    }
    __syncthreads();

    const int w    = t >> 5;
    const int l    = t & 31;
    const int pair = w & 7;        // query group: rows Q0+pair*16 .. +15
    const int h    = w >> 3;       // key-span half: 0 -> lk [0,80), 1 -> lk [80,144)
    const int NT    = h ? 8  : 10; // S n-tiles this warp
    const int NKS   = h ? 4  : 5;  // PV k-steps this warp
    const int lkoff = h ? 80 : 0;

    // ---- load Q A-fragments (4 k-steps, hi+lo) ----
    uint32_t aqh[4][4], aql[4][4];
    {
        uint32_t qaddr = sb + QH_OFF + (uint32_t)(pair * 16 + (l & 15)) * ROWB + ((l >> 4) * 16);
        #pragma unroll
        for (int ks = 0; ks < 4; ks++) {
            ldsm4(aqh[ks], qaddr + ks * 32);
            ldsm4(aql[ks], qaddr + (QL_OFF - QH_OFF) + ks * 32);
        }
    }

    // ---- S = Q K^T over this half's key span ----
    float sacc[10][4];
    #pragma unroll
    for (int nt = 0; nt < 10; nt++)
        #pragma unroll
        for (int i = 0; i < 4; i++) sacc[nt][i] = 0.f;

    {
        uint32_t kaddr = sb + KH_OFF + (uint32_t)(pair * 16 + lkoff + (l & 7)) * ROWB + ((l >> 3) & 1) * 16;
        #pragma unroll
        for (int nt = 0; nt < 10; nt++) {
            if (nt >= NT) break;
            #pragma unroll
            for (int ks = 0; ks < 4; ks++) {
                uint32_t a0 = kaddr + (uint32_t)nt * 8 * ROWB + ks * 32;
                uint32_t bh0, bh1, bl0, bl1;
                ldsm2(bh0, bh1, a0);
                ldsm2(bl0, bl1, a0 + (KL_OFF - KH_OFF));
                mma_bf16(sacc[nt], aqh[ks], bh0, bh1);
                mma_bf16(sacc[nt], aqh[ks], bl0, bl1);
                mma_bf16(sacc[nt], aql[ks], bh0, bh1);
            }
        }
    }

    // ---- masked exp + partial row sums (scores already in log2 domain) ----
    const int jbase = Q0 - WIN + pair * 16;
    const int m0 = l >> 2;
    const int cc = (l & 3) * 2;
    float rs0 = 0.f, rs1 = 0.f;
    #pragma unroll
    for (int nt = 0; nt < 10; nt++) {
        if (nt >= NT) break;
        int lk = lkoff + nt * 8 + cc;
        bool ok0a = ((unsigned)(lk     - m0) <= 2u * WIN) && ((unsigned)(jbase + lk)     < SEQ);
        bool ok0b = ((unsigned)(lk + 1 - m0) <= 2u * WIN) && ((unsigned)(jbase + lk + 1) < SEQ);
        bool ok1a = ((unsigned)(lk     - m0 - 8) <= 2u * WIN) && ((unsigned)(jbase + lk)     < SEQ);
        bool ok1b = ((unsigned)(lk + 1 - m0 - 8) <= 2u * WIN) && ((unsigned)(jbase + lk + 1) < SEQ);
        float p0 = ok0a ? ex2f(sacc[nt][0]) : 0.f;
        float p1 = ok0b ? ex2f(sacc[nt][1]) : 0.f;
        float p2 = ok1a ? ex2f(sacc[nt][2]) : 0.f;
        float p3 = ok1b ? ex2f(sacc[nt][3]) : 0.f;
        sacc[nt][0] = p0; sacc[nt][1] = p1; sacc[nt][2] = p2; sacc[nt][3] = p3;
        rs0 += p0 + p1;
        rs1 += p2 + p3;
    }
    rs0 += __shfl_xor_sync(0xFFFFFFFFu, rs0, 1);
    rs0 += __shfl_xor_sync(0xFFFFFFFFu, rs0, 2);
    rs1 += __shfl_xor_sync(0xFFFFFFFFu, rs1, 1);
    rs1 += __shfl_xor_sync(0xFFFFFFFFu, rs1, 2);

    // ---- O_partial = P_partial V_partial ----
    float oacc[8][4];
    #pragma unroll
    for (int nt = 0; nt < 8; nt++)
        #pragma unroll
        for (int i = 0; i < 4; i++) oacc[nt][i] = 0.f;

    {
        uint32_t vaddr = sb + VH_OFF + (uint32_t)(pair * 16 + lkoff + (l & 7) + ((l >> 3) & 1) * 8) * ROWB;
        #pragma unroll
        for (int ks = 0; ks < 5; ks++) {
            if (ks >= NKS) break;
            uint32_t ah[4], al[4];
            split2(sacc[2*ks][0],   sacc[2*ks][1],   ah[0], al[0]);
            split2(sacc[2*ks][2],   sacc[2*ks][3],   ah[1], al[1]);
            split2(sacc[2*ks+1][0], sacc[2*ks+1][1], ah[2], al[2]);
            split2(sacc[2*ks+1][2], sacc[2*ks+1][3], ah[3], al[3]);
            #pragma unroll
            for (int nt = 0; nt < 8; nt++) {
                uint32_t a0 = vaddr + (uint32_t)ks * 16 * ROWB + nt * 16;
                uint32_t bh0, bh1, bl0, bl1;
                ldsm2t(bh0, bh1, a0);
                ldsm2t(bl0, bl1, a0 + (VL_OFF - VH_OFF));
                mma_bf16(oacc[nt], ah, bh0, bh1);
                mma_bf16(oacc[nt], ah, bl0, bl1);
                mma_bf16(oacc[nt], al, bh0, bh1);
            }
        }
    }

    // ---- combine halves via smem (reuse Q-tile region, now dead) ----
    float* cb = (float*)(smem + QH_OFF);
    __syncthreads();                               // all Q-frag reads done
    if (h == 1) {
        float* p0 = cb + (size_t)(pair * 16 + m0) * CBS;
        float* p1 = p0 + 8 * CBS;
        #pragma unroll
        for (int nt = 0; nt < 8; nt++) {
            *(float2*)(p0 + nt * 8 + cc) = make_float2(oacc[nt][0], oacc[nt][1]);
            *(float2*)(p1 + nt * 8 + cc) = make_float2(oacc[nt][2], oacc[nt][3]);
        }
        if (cc == 0) { p0[64] = rs0; p1[64] = rs1; }
    }
    __syncthreads();
    if (h == 0) {
        const float* p0 = cb + (size_t)(pair * 16 + m0) * CBS;
        const float* p1 = p0 + 8 * CBS;
        #pragma unroll
        for (int nt = 0; nt < 8; nt++) {
            float2 u0 = *(const float2*)(p0 + nt * 8 + cc);
            float2 u1 = *(const float2*)(p1 + nt * 8 + cc);
            oacc[nt][0] += u0.x; oacc[nt][1] += u0.y;
            oacc[nt][2] += u1.x; oacc[nt][3] += u1.y;
        }
        float inv0 = 1.f / (rs0 + p0[64]);
        float inv1 = 1.f / (rs1 + p1[64]);
        float* orow0 = ob + (size_t)(Q0 + pair * 16 + m0) * DIM;
        float* orow1 = orow0 + 8 * DIM;
        #pragma unroll
        for (int nt = 0; nt < 8; nt++) {
            *(float2*)(orow0 + nt * 8 + cc) = make_float2(oacc[nt][0] * inv0, oacc[nt][1] * inv0);
            *(float2*)(orow1 + nt * 8 + cc) = make_float2(oacc[nt][2] * inv1, oacc[nt][3] * inv1);
        }
    }
}

extern "C" void kernel_launch(void* const* d_in, const int* in_sizes, int n_in,
                              void* d_out, int out_size)
{
    const float* q = (const float*)d_in[0];
    const float* k = (const float*)d_in[1];
    const float* v = (const float*)d_in[2];
    float* out = (float*)d_out;

    int B = in_sizes[0] / (SEQ * DIM);

    cudaFuncSetAttribute(swa_hmma_kernel,
                         cudaFuncAttributeMaxDynamicSharedMemorySize, SMEM_BYTES);

    dim3 grid(B * (SEQ / QPB));
    swa_hmma_kernel<<<grid, NTHREADS, SMEM_BYTES>>>(q, k, v, out);
}